// round 1
// baseline (speedup 1.0000x reference)
#include <cuda_runtime.h>
#include <math.h>

#define T_TOK 2176
#define HS    2048
#define NQKV  3072
#define NH    16
#define NKV   4
#define HD    128
#define MMETA 128
#define WWIN  512
#define SCALE_F 0.08838834764831845f

// scratch: raw qkv projections (q,k roped in place)
__device__ float g_qkv[T_TOK * NQKV];

// ---------------------------------------------------------------------------
// Stage 1: QKV GEMM  C[T,3072] = A[T,2048] @ W[2048,3072] + bias
// 128x128 block tile, BK=16, 256 threads, 8x8 microtile.
// ---------------------------------------------------------------------------
__global__ __launch_bounds__(256, 2)
void qkv_gemm_kernel(const float* __restrict__ A,
                     const float* __restrict__ B,
                     const float* __restrict__ bias) {
    __shared__ float Ash[16][132];   // k-major (transposed), pad 132 keeps float4 reads aligned
    __shared__ float Bsh[16][128];

    const int bm = blockIdx.y * 128;
    const int bn = blockIdx.x * 128;
    const int tid = threadIdx.x;
    const int tx = tid & 15;
    const int ty = tid >> 4;
    const int m0 = ty * 8;
    const int n0 = tx * 8;

    float acc[8][8];
#pragma unroll
    for (int i = 0; i < 8; ++i)
#pragma unroll
        for (int j = 0; j < 8; ++j) acc[i][j] = 0.f;

    const int a_m = tid >> 2;          // 0..63 (+64 second pass)
    const int a_k = (tid & 3) * 4;     // 0,4,8,12
    const int b_k = tid >> 5;          // 0..7 (+8 second pass)
    const int b_n = (tid & 31) * 4;    // 0..124

    for (int k0 = 0; k0 < HS; k0 += 16) {
#pragma unroll
        for (int p = 0; p < 2; ++p) {
            int m = a_m + p * 64;
            float4 v = *(const float4*)&A[(size_t)(bm + m) * HS + k0 + a_k];
            Ash[a_k + 0][m] = v.x;
            Ash[a_k + 1][m] = v.y;
            Ash[a_k + 2][m] = v.z;
            Ash[a_k + 3][m] = v.w;
        }
#pragma unroll
        for (int p = 0; p < 2; ++p) {
            int k = b_k + p * 8;
            *(float4*)&Bsh[k][b_n] = *(const float4*)&B[(size_t)(k0 + k) * NQKV + bn + b_n];
        }
        __syncthreads();
#pragma unroll
        for (int kk = 0; kk < 16; ++kk) {
            float a[8], b[8];
            *(float4*)&a[0] = *(float4*)&Ash[kk][m0];
            *(float4*)&a[4] = *(float4*)&Ash[kk][m0 + 4];
            *(float4*)&b[0] = *(float4*)&Bsh[kk][n0];
            *(float4*)&b[4] = *(float4*)&Bsh[kk][n0 + 4];
#pragma unroll
            for (int i = 0; i < 8; ++i)
#pragma unroll
                for (int j = 0; j < 8; ++j)
                    acc[i][j] += a[i] * b[j];
        }
        __syncthreads();
    }

#pragma unroll
    for (int i = 0; i < 8; ++i) {
        int m = bm + m0 + i;
#pragma unroll
        for (int j = 0; j < 8; j += 4) {
            float4 o;
            o.x = acc[i][j + 0] + bias[bn + n0 + j + 0];
            o.y = acc[i][j + 1] + bias[bn + n0 + j + 1];
            o.z = acc[i][j + 2] + bias[bn + n0 + j + 2];
            o.w = acc[i][j + 3] + bias[bn + n0 + j + 3];
            *(float4*)&g_qkv[(size_t)m * NQKV + bn + n0 + j] = o;
        }
    }
}

// ---------------------------------------------------------------------------
// Stage 2: in-place RoPE on q (heads 0..15) and k (heads 16..19) columns.
// One thread per (token, head, pair).
// ---------------------------------------------------------------------------
__global__ void rope_kernel(const int* __restrict__ positions) {
    int idx = blockIdx.x * blockDim.x + threadIdx.x;
    if (idx >= T_TOK * 20 * 64) return;
    int i  = idx & 63;
    int hh = (idx >> 6) % 20;
    int t  = idx / (64 * 20);

    // inv_freq in double, rounded to fp32 (matches jax fp32 pow to ~1 ulp),
    // angle in fp32 like the reference.
    float inv = (float)exp(-(double)(2 * i) * (1.0 / 128.0) * log(10000.0));
    float ang = (float)positions[t] * inv;
    float c = cosf(ang);
    float s = sinf(ang);

    float* base = &g_qkv[(size_t)t * NQKV + hh * HD];
    float x1 = base[i];
    float x2 = base[i + 64];
    base[i]      = x1 * c - x2 * s;
    base[i + 64] = x2 * c + x1 * s;
}

// ---------------------------------------------------------------------------
// Stage 3: attention. Block = (q-tile of 64, head). 256 threads.
// Online-softmax flash loop over key tiles of 64:
//   meta queries (t<128): causal over meta keys only (tiles 0..qt)
//   local queries: meta tiles 0,1 (unmasked) + window tiles max(2,qt-8)..qt
// ---------------------------------------------------------------------------
#define QPITCH 68
#define ATTN_SMEM_FLOATS (128*QPITCH + 128*QPITCH + 64*128 + 64*QPITCH)

__global__ __launch_bounds__(256, 1)
void attn_kernel(float* __restrict__ out) {
    extern __shared__ float smem[];
    float* Qs = smem;                    // [128][68] k-major: Qs[kk*68 + r]
    float* Ks = Qs + 128 * QPITCH;       // [128][68] k-major: Ks[kk*68 + j]
    float* Vs = Ks + 128 * QPITCH;       // [64][128]: Vs[j*128 + c]
    float* Ps = Vs + 64 * 128;           // [64][68]:  Ps[r*68 + j]

    const int qt  = blockIdx.x;
    const int h   = blockIdx.y;
    const int t0  = qt * 64;
    const int kvh = h >> 2;
    const int tid = threadIdx.x;
    const int tx  = tid & 15;
    const int ty  = tid >> 4;
    const int r0  = ty * 4;
    const int j0  = tx * 4;
    const int c0  = tx * 8;

    // transpose-loader (Q,K): warp covers 8 rows x 16 k per pass (2-way smem conflicts)
    const int tkg  = (tid & 3) * 4;
    const int trow = (tid >> 2) & 7;
    const int tk16 = (tid >> 5) * 16;
    // direct loader (V): conflict-free row copy
    const int vk = (tid & 31) * 4;
    const int vr = tid >> 5;

    // load Q tile (transposed)
#pragma unroll
    for (int p = 0; p < 8; ++p) {
        int r  = trow + p * 8;
        int kb = tk16 + tkg;
        float4 q4 = *(const float4*)&g_qkv[(size_t)(t0 + r) * NQKV + h * HD + kb];
        Qs[(kb + 0) * QPITCH + r] = q4.x;
        Qs[(kb + 1) * QPITCH + r] = q4.y;
        Qs[(kb + 2) * QPITCH + r] = q4.z;
        Qs[(kb + 3) * QPITCH + r] = q4.w;
    }

    float m_st[4], l_st[4], o[4][8];
#pragma unroll
    for (int i = 0; i < 4; ++i) { m_st[i] = -3.0e38f; l_st[i] = 0.f; }
#pragma unroll
    for (int i = 0; i < 4; ++i)
#pragma unroll
        for (int c = 0; c < 8; ++c) o[i][c] = 0.f;

    const int two_phase = (t0 >= MMETA) && (qt >= 10);
    const int nphase = two_phase ? 2 : 1;

    for (int ph = 0; ph < nphase; ++ph) {
        int lo = 0, hi = qt;
        if (two_phase) {
            if (ph == 0) { lo = 0; hi = 1; }
            else         { lo = qt - 8; hi = qt; }
        }
        for (int kt = lo; kt <= hi; ++kt) {
            const int s0 = kt * 64;

            // load K (transposed) + V (direct)
#pragma unroll
            for (int p = 0; p < 8; ++p) {
                int r  = trow + p * 8;
                int kb = tk16 + tkg;
                float4 k4 = *(const float4*)&g_qkv[(size_t)(s0 + r) * NQKV + (NH * HD) + kvh * HD + kb];
                Ks[(kb + 0) * QPITCH + r] = k4.x;
                Ks[(kb + 1) * QPITCH + r] = k4.y;
                Ks[(kb + 2) * QPITCH + r] = k4.z;
                Ks[(kb + 3) * QPITCH + r] = k4.w;
                int rv = vr + p * 8;
                *(float4*)&Vs[rv * 128 + vk] =
                    *(const float4*)&g_qkv[(size_t)(s0 + rv) * NQKV + ((NH + NKV) * HD) + kvh * HD + vk];
            }
            __syncthreads();

            // S = Q K^T  (4x4 microtile per thread)
            float acc[4][4];
#pragma unroll
            for (int i = 0; i < 4; ++i)
#pragma unroll
                for (int j = 0; j < 4; ++j) acc[i][j] = 0.f;

#pragma unroll 4
            for (int kk = 0; kk < 128; ++kk) {
                float4 q = *(float4*)&Qs[kk * QPITCH + r0];
                float4 k = *(float4*)&Ks[kk * QPITCH + j0];
                acc[0][0] += q.x * k.x; acc[0][1] += q.x * k.y; acc[0][2] += q.x * k.z; acc[0][3] += q.x * k.w;
                acc[1][0] += q.y * k.x; acc[1][1] += q.y * k.y; acc[1][2] += q.y * k.z; acc[1][3] += q.y * k.w;
                acc[2][0] += q.z * k.x; acc[2][1] += q.z * k.y; acc[2][2] += q.z * k.z; acc[2][3] += q.z * k.w;
                acc[3][0] += q.w * k.x; acc[3][1] += q.w * k.y; acc[3][2] += q.w * k.z; acc[3][3] += q.w * k.w;
            }

            // mask + online softmax (row groups = 16 lanes along tx)
#pragma unroll
            for (int i = 0; i < 4; ++i) {
                int t = t0 + r0 + i;
                float sv[4];
                float rowmax = -3.0e38f;
#pragma unroll
                for (int j = 0; j < 4; ++j) {
                    int s = s0 + j0 + j;
                    float v = acc[i][j] * SCALE_F;
                    bool valid = (t < MMETA) ? (s <= t)
                                             : ((s < MMETA) || ((s <= t) && (t - s < WWIN)));
                    sv[j] = valid ? v : -1.0e30f;
                    rowmax = fmaxf(rowmax, sv[j]);
                }
#pragma unroll
                for (int off = 8; off > 0; off >>= 1)
                    rowmax = fmaxf(rowmax, __shfl_xor_sync(0xffffffffu, rowmax, off));
                float mnew  = fmaxf(m_st[i], rowmax);
                float alpha = __expf(m_st[i] - mnew);
                float4 pv;
                pv.x = __expf(sv[0] - mnew);
                pv.y = __expf(sv[1] - mnew);
                pv.z = __expf(sv[2] - mnew);
                pv.w = __expf(sv[3] - mnew);
                float rsum = pv.x + pv.y + pv.z + pv.w;
                *(float4*)&Ps[(r0 + i) * QPITCH + j0] = pv;
#pragma unroll
                for (int off = 8; off > 0; off >>= 1)
                    rsum += __shfl_xor_sync(0xffffffffu, rsum, off);
                l_st[i] = l_st[i] * alpha + rsum;
                m_st[i] = mnew;
#pragma unroll
                for (int c = 0; c < 8; ++c) o[i][c] *= alpha;
            }
            __syncthreads();

            // O += P V   (4 rows x 8 cols per thread)
#pragma unroll 4
            for (int jj = 0; jj < 64; ++jj) {
                float p0 = Ps[(r0 + 0) * QPITCH + jj];
                float p1 = Ps[(r0 + 1) * QPITCH + jj];
                float p2 = Ps[(r0 + 2) * QPITCH + jj];
                float p3 = Ps[(r0 + 3) * QPITCH + jj];
                float4 va = *(float4*)&Vs[jj * 128 + c0];
                float4 vb = *(float4*)&Vs[jj * 128 + c0 + 4];
                o[0][0] += p0 * va.x; o[0][1] += p0 * va.y; o[0][2] += p0 * va.z; o[0][3] += p0 * va.w;
                o[0][4] += p0 * vb.x; o[0][5] += p0 * vb.y; o[0][6] += p0 * vb.z; o[0][7] += p0 * vb.w;
                o[1][0] += p1 * va.x; o[1][1] += p1 * va.y; o[1][2] += p1 * va.z; o[1][3] += p1 * va.w;
                o[1][4] += p1 * vb.x; o[1][5] += p1 * vb.y; o[1][6] += p1 * vb.z; o[1][7] += p1 * vb.w;
                o[2][0] += p2 * va.x; o[2][1] += p2 * va.y; o[2][2] += p2 * va.z; o[2][3] += p2 * va.w;
                o[2][4] += p2 * vb.x; o[2][5] += p2 * vb.y; o[2][6] += p2 * vb.z; o[2][7] += p2 * vb.w;
                o[3][0] += p3 * va.x; o[3][1] += p3 * va.y; o[3][2] += p3 * va.z; o[3][3] += p3 * va.w;
                o[3][4] += p3 * vb.x; o[3][5] += p3 * vb.y; o[3][6] += p3 * vb.z; o[3][7] += p3 * vb.w;
            }
            __syncthreads();
        }
    }

    // epilogue: normalize and store
#pragma unroll
    for (int i = 0; i < 4; ++i) {
        float inv = 1.0f / l_st[i];
        int t = t0 + r0 + i;
        float4 oa, ob;
        oa.x = o[i][0] * inv; oa.y = o[i][1] * inv; oa.z = o[i][2] * inv; oa.w = o[i][3] * inv;
        ob.x = o[i][4] * inv; ob.y = o[i][5] * inv; ob.z = o[i][6] * inv; ob.w = o[i][7] * inv;
        *(float4*)&out[(size_t)t * (NH * HD) + h * HD + c0]     = oa;
        *(float4*)&out[(size_t)t * (NH * HD) + h * HD + c0 + 4] = ob;
    }
}

// ---------------------------------------------------------------------------
extern "C" void kernel_launch(void* const* d_in, const int* in_sizes, int n_in,
                              void* d_out, int out_size) {
    const float* hs   = (const float*)d_in[0];
    const float* w    = (const float*)d_in[1];
    const float* bias = (const float*)d_in[2];
    const int*   pos  = (const int*)d_in[3];
    float* out = (float*)d_out;

    dim3 gg(NQKV / 128, T_TOK / 128);
    qkv_gemm_kernel<<<gg, 256>>>(hs, w, bias);

    int nrope = T_TOK * 20 * 64;
    rope_kernel<<<(nrope + 255) / 256, 256>>>(pos);

    size_t smem_bytes = ATTN_SMEM_FLOATS * sizeof(float);
    cudaFuncSetAttribute(attn_kernel, cudaFuncAttributeMaxDynamicSharedMemorySize,
                         (int)smem_bytes);
    attn_kernel<<<dim3(T_TOK / 64, NH), 256, smem_bytes>>>(out);
}

// round 3
// speedup vs baseline: 1.5011x; 1.5011x over previous
#include <cuda_runtime.h>
#include <cuda_bf16.h>
#include <cstdint>
#include <math.h>

#define T_TOK 2176
#define HS    2048
#define NQKV  3072
#define NH    16
#define NKV   4
#define HD    128
#define MMETA 128
#define WWIN  512
#define SCALE_F 0.08838834764831845f

// ---------------------------------------------------------------------------
// scratch buffers
// ---------------------------------------------------------------------------
__device__ float g_qkv[T_TOK * NQKV];                    // fp32 qkv (roped in place)
__device__ __nv_bfloat16 g_Ahi[T_TOK * HS];
__device__ __nv_bfloat16 g_Alo[T_TOK * HS];
__device__ __nv_bfloat16 g_Bthi[NQKV * HS];              // W transposed [n][k]
__device__ __nv_bfloat16 g_Btlo[NQKV * HS];

__device__ __forceinline__ uint32_t smem_to_u32(const void* p) {
    uint32_t a;
    asm("{ .reg .u64 t; cvta.to.shared.u64 t, %1; cvt.u32.u64 %0, t; }" : "=r"(a) : "l"(p));
    return a;
}

// ---------------------------------------------------------------------------
// Stage 0a: split hidden_states fp32 -> bf16 hi/lo
// ---------------------------------------------------------------------------
__global__ void split_a_kernel(const float* __restrict__ A) {
    int i = (blockIdx.x * blockDim.x + threadIdx.x) * 4;
    if (i >= T_TOK * HS) return;
    float4 v = *(const float4*)&A[i];
    __nv_bfloat16 h0 = __float2bfloat16(v.x);
    __nv_bfloat16 h1 = __float2bfloat16(v.y);
    __nv_bfloat16 h2 = __float2bfloat16(v.z);
    __nv_bfloat16 h3 = __float2bfloat16(v.w);
    __nv_bfloat162 hi01, hi23, lo01, lo23;
    hi01.x = h0; hi01.y = h1; hi23.x = h2; hi23.y = h3;
    lo01.x = __float2bfloat16(v.x - __bfloat162float(h0));
    lo01.y = __float2bfloat16(v.y - __bfloat162float(h1));
    lo23.x = __float2bfloat16(v.z - __bfloat162float(h2));
    lo23.y = __float2bfloat16(v.w - __bfloat162float(h3));
    *(__nv_bfloat162*)&g_Ahi[i]     = hi01;
    *(__nv_bfloat162*)&g_Ahi[i + 2] = hi23;
    *(__nv_bfloat162*)&g_Alo[i]     = lo01;
    *(__nv_bfloat162*)&g_Alo[i + 2] = lo23;
}

// ---------------------------------------------------------------------------
// Stage 0b: transpose + split W[2048,3072] -> Bt_hi/lo[3072][2048]
// ---------------------------------------------------------------------------
__global__ void split_w_kernel(const float* __restrict__ W) {
    __shared__ float tile[32][33];
    int n0 = blockIdx.x * 32;
    int k0 = blockIdx.y * 32;
    int tx = threadIdx.x;
    int ty = threadIdx.y;
#pragma unroll
    for (int p = 0; p < 4; ++p) {
        int k = ty + p * 8;
        tile[k][tx] = W[(size_t)(k0 + k) * NQKV + n0 + tx];
    }
    __syncthreads();
#pragma unroll
    for (int p = 0; p < 4; ++p) {
        int n = ty + p * 8;
        float v = tile[tx][n];
        __nv_bfloat16 hi = __float2bfloat16(v);
        __nv_bfloat16 lo = __float2bfloat16(v - __bfloat162float(hi));
        size_t o = (size_t)(n0 + n) * HS + k0 + tx;
        g_Bthi[o] = hi;
        g_Btlo[o] = lo;
    }
}

// ---------------------------------------------------------------------------
// Stage 1: bf16x3 GEMM via mma.sync (HMMA).  C[T,3072] = A @ W + bias.
// CTA 128x128, BK=32, 8 warps (warp tile 64x32), cp.async 2-stage pipeline.
// smem pitch: 32 bf16 + 8 pad = 40 bf16 = 80B per row (conflict-free LDSM).
// ---------------------------------------------------------------------------
#define BK 32
#define LDT 40                       // bf16 per smem row (80 bytes)
#define TILE_B (128 * 80)            // 10240 bytes per tile
#define STAGE_B (4 * TILE_B)         // Ahi, Alo, Bhi, Blo
#define GEMM_SMEM (2 * STAGE_B)      // 81920

__device__ __forceinline__ void ldsm_x4(uint32_t* r, uint32_t addr) {
    asm volatile("ldmatrix.sync.aligned.m8n8.x4.shared.b16 {%0,%1,%2,%3}, [%4];"
                 : "=r"(r[0]), "=r"(r[1]), "=r"(r[2]), "=r"(r[3]) : "r"(addr));
}
__device__ __forceinline__ void ldsm_x2(uint32_t* r, uint32_t addr) {
    asm volatile("ldmatrix.sync.aligned.m8n8.x2.shared.b16 {%0,%1}, [%2];"
                 : "=r"(r[0]), "=r"(r[1]) : "r"(addr));
}
__device__ __forceinline__ void mma_bf16(float* c, const uint32_t* a, const uint32_t* b) {
    asm volatile(
        "mma.sync.aligned.m16n8k16.row.col.f32.bf16.bf16.f32 "
        "{%0,%1,%2,%3}, {%4,%5,%6,%7}, {%8,%9}, {%0,%1,%2,%3};"
        : "+f"(c[0]), "+f"(c[1]), "+f"(c[2]), "+f"(c[3])
        : "r"(a[0]), "r"(a[1]), "r"(a[2]), "r"(a[3]), "r"(b[0]), "r"(b[1]));
}
__device__ __forceinline__ void cp_async16(uint32_t dst, const void* src) {
    asm volatile("cp.async.ca.shared.global [%0], [%1], 16;" :: "r"(dst), "l"(src) : "memory");
}
#define CP_COMMIT() asm volatile("cp.async.commit_group;" ::: "memory")
#define CP_WAIT1()  asm volatile("cp.async.wait_group 1;" ::: "memory")

__global__ __launch_bounds__(256, 2)
void qkv_mma_kernel(const float* __restrict__ bias) {
    extern __shared__ char smem[];
    const uint32_t sb = smem_to_u32(smem);
    const int tid  = threadIdx.x;
    const int wid  = tid >> 5;
    const int lane = tid & 31;
    const int bm = blockIdx.y * 128;
    const int bn = blockIdx.x * 128;
    const int wm = (wid >> 2) * 64;      // 0 or 64
    const int wn = (wid & 3) * 32;       // 0,32,64,96

    const __nv_bfloat16* srcs[4] = {
        g_Ahi + (size_t)bm * HS, g_Alo + (size_t)bm * HS,
        g_Bthi + (size_t)bn * HS, g_Btlo + (size_t)bn * HS };

    // per-thread loader chunks: 2048 16B-chunks/stage, 8 per thread
    auto issue_stage = [&](int c, int s) {
#pragma unroll
        for (int q = 0; q < 8; ++q) {
            int idx = q * 256 + tid;
            int t   = idx >> 9;
            int cc  = idx & 511;
            int row = cc >> 2;
            int seg = cc & 3;
            const __nv_bfloat16* src = srcs[t] + (size_t)row * HS + c * BK + seg * 8;
            uint32_t dst = sb + s * STAGE_B + t * TILE_B + row * 80 + seg * 16;
            cp_async16(dst, src);
        }
    };

    float acc[4][4][4];
#pragma unroll
    for (int i = 0; i < 4; ++i)
#pragma unroll
        for (int j = 0; j < 4; ++j)
#pragma unroll
            for (int q = 0; q < 4; ++q) acc[i][j][q] = 0.f;

    issue_stage(0, 0); CP_COMMIT();
    issue_stage(1, 1); CP_COMMIT();

    const int NCH = HS / BK;   // 64
    for (int c = 0; c < NCH; ++c) {
        CP_WAIT1();
        __syncthreads();

        const uint32_t base  = sb + (c & 1) * STAGE_B;
        const int arow = wm + (lane & 15);
        const int acolh = (lane >> 4) << 3;          // 0 or 8 (bf16)
        const int brow = wn + (lane & 7);
        const int bcolh = ((lane >> 3) & 1) << 3;

#pragma unroll
        for (int ks = 0; ks < 2; ++ks) {
            uint32_t ahi[4][4], alo[4][4];
#pragma unroll
            for (int i = 0; i < 4; ++i) {
                uint32_t aaddr = base + (arow + i * 16) * 80 + (acolh + ks * 16) * 2;
                ldsm_x4(ahi[i], aaddr);
                ldsm_x4(alo[i], aaddr + TILE_B);
            }
#pragma unroll
            for (int j = 0; j < 4; ++j) {
                uint32_t bh[2], bl[2];
                uint32_t baddr = base + 2 * TILE_B + (brow + j * 8) * 80 + (bcolh + ks * 16) * 2;
                ldsm_x2(bh, baddr);
                ldsm_x2(bl, baddr + TILE_B);
#pragma unroll
                for (int i = 0; i < 4; ++i) {
                    mma_bf16(acc[i][j], ahi[i], bh);
                    mma_bf16(acc[i][j], ahi[i], bl);
                    mma_bf16(acc[i][j], alo[i], bh);
                }
            }
        }
        __syncthreads();
        if (c + 2 < NCH) issue_stage(c + 2, c & 1);
        CP_COMMIT();
    }

    // epilogue: write fp32 + bias to g_qkv
    const int r  = lane >> 2;
    const int cp = (lane & 3) * 2;
#pragma unroll
    for (int i = 0; i < 4; ++i) {
#pragma unroll
        for (int j = 0; j < 4; ++j) {
            int gcol = bn + wn + j * 8 + cp;
            float b0 = bias[gcol], b1 = bias[gcol + 1];
            int grow0 = bm + wm + i * 16 + r;
            float2 v0 = { acc[i][j][0] + b0, acc[i][j][1] + b1 };
            float2 v1 = { acc[i][j][2] + b0, acc[i][j][3] + b1 };
            *(float2*)&g_qkv[(size_t)grow0 * NQKV + gcol]       = v0;
            *(float2*)&g_qkv[(size_t)(grow0 + 8) * NQKV + gcol] = v1;
        }
    }
}

// ---------------------------------------------------------------------------
// Stage 2: RoPE
// ---------------------------------------------------------------------------
__global__ void rope_kernel(const int* __restrict__ positions) {
    int idx = blockIdx.x * blockDim.x + threadIdx.x;
    if (idx >= T_TOK * 20 * 64) return;
    int i  = idx & 63;
    int hh = (idx >> 6) % 20;
    int t  = idx / (64 * 20);

    float inv = (float)exp(-(double)(2 * i) * (1.0 / 128.0) * log(10000.0));
    float ang = (float)positions[t] * inv;
    float c = cosf(ang);
    float s = sinf(ang);

    float* base = &g_qkv[(size_t)t * NQKV + hh * HD];
    float x1 = base[i];
    float x2 = base[i + 64];
    base[i]      = x1 * c - x2 * s;
    base[i + 64] = x2 * c + x1 * s;
}

// ---------------------------------------------------------------------------
// Stage 3: attention (unchanged)
// ---------------------------------------------------------------------------
#define QPITCH 68
#define ATTN_SMEM_FLOATS (128*QPITCH + 128*QPITCH + 64*128 + 64*QPITCH)

__global__ __launch_bounds__(256, 1)
void attn_kernel(float* __restrict__ out) {
    extern __shared__ float smemf[];
    float* Qs = smemf;
    float* Ks = Qs + 128 * QPITCH;
    float* Vs = Ks + 128 * QPITCH;
    float* Ps = Vs + 64 * 128;

    const int qt  = blockIdx.x;
    const int h   = blockIdx.y;
    const int t0  = qt * 64;
    const int kvh = h >> 2;
    const int tid = threadIdx.x;
    const int tx  = tid & 15;
    const int ty  = tid >> 4;
    const int r0  = ty * 4;
    const int j0  = tx * 4;
    const int c0  = tx * 8;

    const int tkg  = (tid & 3) * 4;
    const int trow = (tid >> 2) & 7;
    const int tk16 = (tid >> 5) * 16;
    const int vk = (tid & 31) * 4;
    const int vr = tid >> 5;

#pragma unroll
    for (int p = 0; p < 8; ++p) {
        int r  = trow + p * 8;
        int kb = tk16 + tkg;
        float4 q4 = *(const float4*)&g_qkv[(size_t)(t0 + r) * NQKV + h * HD + kb];
        Qs[(kb + 0) * QPITCH + r] = q4.x;
        Qs[(kb + 1) * QPITCH + r] = q4.y;
        Qs[(kb + 2) * QPITCH + r] = q4.z;
        Qs[(kb + 3) * QPITCH + r] = q4.w;
    }

    float m_st[4], l_st[4], o[4][8];
#pragma unroll
    for (int i = 0; i < 4; ++i) { m_st[i] = -3.0e38f; l_st[i] = 0.f; }
#pragma unroll
    for (int i = 0; i < 4; ++i)
#pragma unroll
        for (int c = 0; c < 8; ++c) o[i][c] = 0.f;

    const int two_phase = (t0 >= MMETA) && (qt >= 10);
    const int nphase = two_phase ? 2 : 1;

    for (int ph = 0; ph < nphase; ++ph) {
        int lo = 0, hi = qt;
        if (two_phase) {
            if (ph == 0) { lo = 0; hi = 1; }
            else         { lo = qt - 8; hi = qt; }
        }
        for (int kt = lo; kt <= hi; ++kt) {
            const int s0 = kt * 64;
#pragma unroll
            for (int p = 0; p < 8; ++p) {
                int r  = trow + p * 8;
                int kb = tk16 + tkg;
                float4 k4 = *(const float4*)&g_qkv[(size_t)(s0 + r) * NQKV + (NH * HD) + kvh * HD + kb];
                Ks[(kb + 0) * QPITCH + r] = k4.x;
                Ks[(kb + 1) * QPITCH + r] = k4.y;
                Ks[(kb + 2) * QPITCH + r] = k4.z;
                Ks[(kb + 3) * QPITCH + r] = k4.w;
                int rv = vr + p * 8;
                *(float4*)&Vs[rv * 128 + vk] =
                    *(const float4*)&g_qkv[(size_t)(s0 + rv) * NQKV + ((NH + NKV) * HD) + kvh * HD + vk];
            }
            __syncthreads();

            float acc[4][4];
#pragma unroll
            for (int i = 0; i < 4; ++i)
#pragma unroll
                for (int j = 0; j < 4; ++j) acc[i][j] = 0.f;

#pragma unroll 4
            for (int kk = 0; kk < 128; ++kk) {
                float4 q = *(float4*)&Qs[kk * QPITCH + r0];
                float4 k = *(float4*)&Ks[kk * QPITCH + j0];
                acc[0][0] += q.x * k.x; acc[0][1] += q.x * k.y; acc[0][2] += q.x * k.z; acc[0][3] += q.x * k.w;
                acc[1][0] += q.y * k.x; acc[1][1] += q.y * k.y; acc[1][2] += q.y * k.z; acc[1][3] += q.y * k.w;
                acc[2][0] += q.z * k.x; acc[2][1] += q.z * k.y; acc[2][2] += q.z * k.z; acc[2][3] += q.z * k.w;
                acc[3][0] += q.w * k.x; acc[3][1] += q.w * k.y; acc[3][2] += q.w * k.z; acc[3][3] += q.w * k.w;
            }

#pragma unroll
            for (int i = 0; i < 4; ++i) {
                int t = t0 + r0 + i;
                float sv[4];
                float rowmax = -3.0e38f;
#pragma unroll
                for (int j = 0; j < 4; ++j) {
                    int s = s0 + j0 + j;
                    float v = acc[i][j] * SCALE_F;
                    bool valid = (t < MMETA) ? (s <= t)
                                             : ((s < MMETA) || ((s <= t) && (t - s < WWIN)));
                    sv[j] = valid ? v : -1.0e30f;
                    rowmax = fmaxf(rowmax, sv[j]);
                }
#pragma unroll
                for (int off = 8; off > 0; off >>= 1)
                    rowmax = fmaxf(rowmax, __shfl_xor_sync(0xffffffffu, rowmax, off));
                float mnew  = fmaxf(m_st[i], rowmax);
                float alpha = __expf(m_st[i] - mnew);
                float4 pv;
                pv.x = __expf(sv[0] - mnew);
                pv.y = __expf(sv[1] - mnew);
                pv.z = __expf(sv[2] - mnew);
                pv.w = __expf(sv[3] - mnew);
                float rsum = pv.x + pv.y + pv.z + pv.w;
                *(float4*)&Ps[(r0 + i) * QPITCH + j0] = pv;
#pragma unroll
                for (int off = 8; off > 0; off >>= 1)
                    rsum += __shfl_xor_sync(0xffffffffu, rsum, off);
                l_st[i] = l_st[i] * alpha + rsum;
                m_st[i] = mnew;
#pragma unroll
                for (int c = 0; c < 8; ++c) o[i][c] *= alpha;
            }
            __syncthreads();

#pragma unroll 4
            for (int jj = 0; jj < 64; ++jj) {
                float p0 = Ps[(r0 + 0) * QPITCH + jj];
                float p1 = Ps[(r0 + 1) * QPITCH + jj];
                float p2 = Ps[(r0 + 2) * QPITCH + jj];
                float p3 = Ps[(r0 + 3) * QPITCH + jj];
                float4 va = *(float4*)&Vs[jj * 128 + c0];
                float4 vb = *(float4*)&Vs[jj * 128 + c0 + 4];
                o[0][0] += p0 * va.x; o[0][1] += p0 * va.y; o[0][2] += p0 * va.z; o[0][3] += p0 * va.w;
                o[0][4] += p0 * vb.x; o[0][5] += p0 * vb.y; o[0][6] += p0 * vb.z; o[0][7] += p0 * vb.w;
                o[1][0] += p1 * va.x; o[1][1] += p1 * va.y; o[1][2] += p1 * va.z; o[1][3] += p1 * va.w;
                o[1][4] += p1 * vb.x; o[1][5] += p1 * vb.y; o[1][6] += p1 * vb.z; o[1][7] += p1 * vb.w;
                o[2][0] += p2 * va.x; o[2][1] += p2 * va.y; o[2][2] += p2 * va.z; o[2][3] += p2 * va.w;
                o[2][4] += p2 * vb.x; o[2][5] += p2 * vb.y; o[2][6] += p2 * vb.z; o[2][7] += p2 * vb.w;
                o[3][0] += p3 * va.x; o[3][1] += p3 * va.y; o[3][2] += p3 * va.z; o[3][3] += p3 * va.w;
                o[3][4] += p3 * vb.x; o[3][5] += p3 * vb.y; o[3][6] += p3 * vb.z; o[3][7] += p3 * vb.w;
            }
            __syncthreads();
        }
    }

#pragma unroll
    for (int i = 0; i < 4; ++i) {
        float inv = 1.0f / l_st[i];
        int t = t0 + r0 + i;
        float4 oa, ob;
        oa.x = o[i][0] * inv; oa.y = o[i][1] * inv; oa.z = o[i][2] * inv; oa.w = o[i][3] * inv;
        ob.x = o[i][4] * inv; ob.y = o[i][5] * inv; ob.z = o[i][6] * inv; ob.w = o[i][7] * inv;
        *(float4*)&out[(size_t)t * (NH * HD) + h * HD + c0]     = oa;
        *(float4*)&out[(size_t)t * (NH * HD) + h * HD + c0 + 4] = ob;
    }
}

// ---------------------------------------------------------------------------
extern "C" void kernel_launch(void* const* d_in, const int* in_sizes, int n_in,
                              void* d_out, int out_size) {
    const float* hs   = (const float*)d_in[0];
    const float* w    = (const float*)d_in[1];
    const float* bias = (const float*)d_in[2];
    const int*   pos  = (const int*)d_in[3];
    float* out = (float*)d_out;

    int na = T_TOK * HS / 4;
    split_a_kernel<<<(na + 255) / 256, 256>>>(hs);
    split_w_kernel<<<dim3(NQKV / 32, HS / 32), dim3(32, 8)>>>(w);

    cudaFuncSetAttribute(qkv_mma_kernel, cudaFuncAttributeMaxDynamicSharedMemorySize, GEMM_SMEM);
    qkv_mma_kernel<<<dim3(NQKV / 128, T_TOK / 128), 256, GEMM_SMEM>>>(bias);

    int nrope = T_TOK * 20 * 64;
    rope_kernel<<<(nrope + 255) / 256, 256>>>(pos);

    size_t smem_bytes = ATTN_SMEM_FLOATS * sizeof(float);
    cudaFuncSetAttribute(attn_kernel, cudaFuncAttributeMaxDynamicSharedMemorySize, (int)smem_bytes);
    attn_kernel<<<dim3(T_TOK / 64, NH), 256, smem_bytes>>>(out);
}

// round 4
// speedup vs baseline: 2.7700x; 1.8453x over previous
#include <cuda_runtime.h>
#include <cuda_bf16.h>
#include <cstdint>
#include <math.h>

#define T_TOK 2176
#define HS    2048
#define NQKV  3072
#define NH    16
#define NKV   4
#define HD    128
#define MMETA 128
#define WWIN  512
#define SCALE_F 0.08838834764831845f
#define NEGV  -1.0e30f

// ---------------------------------------------------------------------------
// scratch buffers
// ---------------------------------------------------------------------------
__device__ float g_qkv[T_TOK * NQKV];                    // fp32 qkv (q roped+scaled in place)
__device__ __nv_bfloat16 g_Ahi[T_TOK * HS];
__device__ __nv_bfloat16 g_Alo[T_TOK * HS];
__device__ __nv_bfloat16 g_Bthi[NQKV * HS];              // W transposed [n][k]
__device__ __nv_bfloat16 g_Btlo[NQKV * HS];
__device__ __nv_bfloat16 g_Khi[T_TOK * NKV * HD];        // roped K split [t][kvh*128+i]
__device__ __nv_bfloat16 g_Klo[T_TOK * NKV * HD];
__device__ __nv_bfloat16 g_Vhi[T_TOK * NKV * HD];
__device__ __nv_bfloat16 g_Vlo[T_TOK * NKV * HD];

__device__ __forceinline__ uint32_t smem_to_u32(const void* p) {
    uint32_t a;
    asm("{ .reg .u64 t; cvta.to.shared.u64 t, %1; cvt.u32.u64 %0, t; }" : "=r"(a) : "l"(p));
    return a;
}
__device__ __forceinline__ uint32_t cvt_bf16x2(float hi, float lo) {
    uint32_t d;
    asm("cvt.rn.bf16x2.f32 %0, %1, %2;" : "=r"(d) : "f"(hi), "f"(lo));
    return d;
}
__device__ __forceinline__ void ldsm_x4(uint32_t* r, uint32_t addr) {
    asm volatile("ldmatrix.sync.aligned.m8n8.x4.shared.b16 {%0,%1,%2,%3}, [%4];"
                 : "=r"(r[0]), "=r"(r[1]), "=r"(r[2]), "=r"(r[3]) : "r"(addr));
}
__device__ __forceinline__ void ldsm_x4t(uint32_t* r, uint32_t addr) {
    asm volatile("ldmatrix.sync.aligned.m8n8.x4.trans.shared.b16 {%0,%1,%2,%3}, [%4];"
                 : "=r"(r[0]), "=r"(r[1]), "=r"(r[2]), "=r"(r[3]) : "r"(addr));
}
__device__ __forceinline__ void ldsm_x2(uint32_t* r, uint32_t addr) {
    asm volatile("ldmatrix.sync.aligned.m8n8.x2.shared.b16 {%0,%1}, [%2];"
                 : "=r"(r[0]), "=r"(r[1]) : "r"(addr));
}
__device__ __forceinline__ void mma_bf16(float* c, const uint32_t* a, const uint32_t* b) {
    asm volatile(
        "mma.sync.aligned.m16n8k16.row.col.f32.bf16.bf16.f32 "
        "{%0,%1,%2,%3}, {%4,%5,%6,%7}, {%8,%9}, {%0,%1,%2,%3};"
        : "+f"(c[0]), "+f"(c[1]), "+f"(c[2]), "+f"(c[3])
        : "r"(a[0]), "r"(a[1]), "r"(a[2]), "r"(a[3]), "r"(b[0]), "r"(b[1]));
}
__device__ __forceinline__ void cp_async16(uint32_t dst, const void* src) {
    asm volatile("cp.async.ca.shared.global [%0], [%1], 16;" :: "r"(dst), "l"(src) : "memory");
}
#define CP_COMMIT() asm volatile("cp.async.commit_group;" ::: "memory")
#define CP_WAIT1()  asm volatile("cp.async.wait_group 1;" ::: "memory")

// ---------------------------------------------------------------------------
// Stage 0a: split hidden_states fp32 -> bf16 hi/lo
// ---------------------------------------------------------------------------
__global__ void split_a_kernel(const float* __restrict__ A) {
    int i = (blockIdx.x * blockDim.x + threadIdx.x) * 4;
    if (i >= T_TOK * HS) return;
    float4 v = *(const float4*)&A[i];
    __nv_bfloat16 h0 = __float2bfloat16(v.x);
    __nv_bfloat16 h1 = __float2bfloat16(v.y);
    __nv_bfloat16 h2 = __float2bfloat16(v.z);
    __nv_bfloat16 h3 = __float2bfloat16(v.w);
    __nv_bfloat162 hi01, hi23, lo01, lo23;
    hi01.x = h0; hi01.y = h1; hi23.x = h2; hi23.y = h3;
    lo01.x = __float2bfloat16(v.x - __bfloat162float(h0));
    lo01.y = __float2bfloat16(v.y - __bfloat162float(h1));
    lo23.x = __float2bfloat16(v.z - __bfloat162float(h2));
    lo23.y = __float2bfloat16(v.w - __bfloat162float(h3));
    *(__nv_bfloat162*)&g_Ahi[i]     = hi01;
    *(__nv_bfloat162*)&g_Ahi[i + 2] = hi23;
    *(__nv_bfloat162*)&g_Alo[i]     = lo01;
    *(__nv_bfloat162*)&g_Alo[i + 2] = lo23;
}

// ---------------------------------------------------------------------------
// Stage 0b: transpose + split W[2048,3072] -> Bt_hi/lo[3072][2048]
// ---------------------------------------------------------------------------
__global__ void split_w_kernel(const float* __restrict__ W) {
    __shared__ float tile[32][33];
    int n0 = blockIdx.x * 32;
    int k0 = blockIdx.y * 32;
    int tx = threadIdx.x;
    int ty = threadIdx.y;
#pragma unroll
    for (int p = 0; p < 4; ++p) {
        int k = ty + p * 8;
        tile[k][tx] = W[(size_t)(k0 + k) * NQKV + n0 + tx];
    }
    __syncthreads();
#pragma unroll
    for (int p = 0; p < 4; ++p) {
        int n = ty + p * 8;
        float v = tile[tx][n];
        __nv_bfloat16 hi = __float2bfloat16(v);
        __nv_bfloat16 lo = __float2bfloat16(v - __bfloat162float(hi));
        size_t o = (size_t)(n0 + n) * HS + k0 + tx;
        g_Bthi[o] = hi;
        g_Btlo[o] = lo;
    }
}

// ---------------------------------------------------------------------------
// Stage 1: bf16x3 GEMM via mma.sync (unchanged from R3)
// ---------------------------------------------------------------------------
#define BK 32
#define TILE_B (128 * 80)
#define STAGE_B (4 * TILE_B)
#define GEMM_SMEM (2 * STAGE_B)

__global__ __launch_bounds__(256, 2)
void qkv_mma_kernel(const float* __restrict__ bias) {
    extern __shared__ char smem[];
    const uint32_t sb = smem_to_u32(smem);
    const int tid  = threadIdx.x;
    const int wid  = tid >> 5;
    const int lane = tid & 31;
    const int bm = blockIdx.y * 128;
    const int bn = blockIdx.x * 128;
    const int wm = (wid >> 2) * 64;
    const int wn = (wid & 3) * 32;

    const __nv_bfloat16* srcs[4] = {
        g_Ahi + (size_t)bm * HS, g_Alo + (size_t)bm * HS,
        g_Bthi + (size_t)bn * HS, g_Btlo + (size_t)bn * HS };

    auto issue_stage = [&](int c, int s) {
#pragma unroll
        for (int q = 0; q < 8; ++q) {
            int idx = q * 256 + tid;
            int t   = idx >> 9;
            int cc  = idx & 511;
            int row = cc >> 2;
            int seg = cc & 3;
            const __nv_bfloat16* src = srcs[t] + (size_t)row * HS + c * BK + seg * 8;
            uint32_t dst = sb + s * STAGE_B + t * TILE_B + row * 80 + seg * 16;
            cp_async16(dst, src);
        }
    };

    float acc[4][4][4];
#pragma unroll
    for (int i = 0; i < 4; ++i)
#pragma unroll
        for (int j = 0; j < 4; ++j)
#pragma unroll
            for (int q = 0; q < 4; ++q) acc[i][j][q] = 0.f;

    issue_stage(0, 0); CP_COMMIT();
    issue_stage(1, 1); CP_COMMIT();

    const int NCH = HS / BK;
    for (int c = 0; c < NCH; ++c) {
        CP_WAIT1();
        __syncthreads();

        const uint32_t base  = sb + (c & 1) * STAGE_B;
        const int arow = wm + (lane & 15);
        const int acolh = (lane >> 4) << 3;
        const int brow = wn + (lane & 7);
        const int bcolh = ((lane >> 3) & 1) << 3;

#pragma unroll
        for (int ks = 0; ks < 2; ++ks) {
            uint32_t ahi[4][4], alo[4][4];
#pragma unroll
            for (int i = 0; i < 4; ++i) {
                uint32_t aaddr = base + (arow + i * 16) * 80 + (acolh + ks * 16) * 2;
                ldsm_x4(ahi[i], aaddr);
                ldsm_x4(alo[i], aaddr + TILE_B);
            }
#pragma unroll
            for (int j = 0; j < 4; ++j) {
                uint32_t bh[2], bl[2];
                uint32_t baddr = base + 2 * TILE_B + (brow + j * 8) * 80 + (bcolh + ks * 16) * 2;
                ldsm_x2(bh, baddr);
                ldsm_x2(bl, baddr + TILE_B);
#pragma unroll
                for (int i = 0; i < 4; ++i) {
                    mma_bf16(acc[i][j], ahi[i], bh);
                    mma_bf16(acc[i][j], ahi[i], bl);
                    mma_bf16(acc[i][j], alo[i], bh);
                }
            }
        }
        __syncthreads();
        if (c + 2 < NCH) issue_stage(c + 2, c & 1);
        CP_COMMIT();
    }

    const int r  = lane >> 2;
    const int cp = (lane & 3) * 2;
#pragma unroll
    for (int i = 0; i < 4; ++i) {
#pragma unroll
        for (int j = 0; j < 4; ++j) {
            int gcol = bn + wn + j * 8 + cp;
            float b0 = bias[gcol], b1 = bias[gcol + 1];
            int grow0 = bm + wm + i * 16 + r;
            float2 v0 = { acc[i][j][0] + b0, acc[i][j][1] + b1 };
            float2 v1 = { acc[i][j][2] + b0, acc[i][j][3] + b1 };
            *(float2*)&g_qkv[(size_t)grow0 * NQKV + gcol]       = v0;
            *(float2*)&g_qkv[(size_t)(grow0 + 8) * NQKV + gcol] = v1;
        }
    }
}

// ---------------------------------------------------------------------------
// Stage 2: prep — RoPE Q (scaled, in place), RoPE+split K, split V
// ---------------------------------------------------------------------------
__global__ void prep_kernel(const int* __restrict__ positions) {
    int idx = blockIdx.x * blockDim.x + threadIdx.x;
    if (idx >= T_TOK * 24 * 64) return;
    int i = idx & 63;
    int u = (idx >> 6) % 24;
    int t = idx / (24 * 64);

    if (u < 20) {
        float inv = (float)exp(-(double)(2 * i) * (1.0 / 128.0) * log(10000.0));
        float ang = (float)positions[t] * inv;
        float c = cosf(ang);
        float s = sinf(ang);
        if (u < 16) {
            float* b = &g_qkv[(size_t)t * NQKV + u * HD];
            float x1 = b[i], x2 = b[i + 64];
            b[i]      = (x1 * c - x2 * s) * SCALE_F;
            b[i + 64] = (x2 * c + x1 * s) * SCALE_F;
        } else {
            int kvh = u - 16;
            const float* b = &g_qkv[(size_t)t * NQKV + NH * HD + kvh * HD];
            float x1 = b[i], x2 = b[i + 64];
            float y1 = x1 * c - x2 * s;
            float y2 = x2 * c + x1 * s;
            size_t o = (size_t)t * (NKV * HD) + kvh * HD + i;
            __nv_bfloat16 h1 = __float2bfloat16(y1);
            __nv_bfloat16 h2 = __float2bfloat16(y2);
            g_Khi[o]      = h1;
            g_Khi[o + 64] = h2;
            g_Klo[o]      = __float2bfloat16(y1 - __bfloat162float(h1));
            g_Klo[o + 64] = __float2bfloat16(y2 - __bfloat162float(h2));
        }
    } else {
        int kvh = u - 20;
        const float* b = &g_qkv[(size_t)t * NQKV + (NH + NKV) * HD + kvh * HD];
        float y1 = b[i], y2 = b[i + 64];
        size_t o = (size_t)t * (NKV * HD) + kvh * HD + i;
        __nv_bfloat16 h1 = __float2bfloat16(y1);
        __nv_bfloat16 h2 = __float2bfloat16(y2);
        g_Vhi[o]      = h1;
        g_Vhi[o + 64] = h2;
        g_Vlo[o]      = __float2bfloat16(y1 - __bfloat162float(h1));
        g_Vlo[o + 64] = __float2bfloat16(y2 - __bfloat162float(h2));
    }
}

// ---------------------------------------------------------------------------
// Stage 3: attention via mma.sync, split precision, 2 heads per CTA.
// smem per stage: Khi,Klo,Vhi,Vlo each 64 rows x 272B.
// ---------------------------------------------------------------------------
#define APITCH 272
#define ARR_B  (64 * APITCH)      // 17408
#define ASTAGE (4 * ARR_B)        // 69632
#define ATTN_SMEM (2 * ASTAGE)    // 139264

__global__ __launch_bounds__(256, 1)
void attn_mma_kernel(float* __restrict__ out) {
    extern __shared__ char smc[];
    const uint32_t smu = smem_to_u32(smc);
    const int tid  = threadIdx.x;
    const int wid  = tid >> 5;
    const int lane = tid & 31;

    const int qt   = 33 - blockIdx.x;          // largest-first for wave balance
    const int hp   = blockIdx.y;               // head pair 0..7
    const int head = hp * 2 + (wid >> 2);
    const int kvh  = hp >> 1;
    const int t0   = qt * 64;
    const int mrow = (wid & 3) * 16;

    const int r  = lane >> 2;
    const int cc = (lane & 3) * 2;

    // ktile schedule
    int kts[12];
    int nkt = 0;
    if (t0 >= MMETA && qt >= 10) {
        kts[nkt++] = 0; kts[nkt++] = 1;
        for (int k = qt - 8; k <= qt; ++k) kts[nkt++] = k;
    } else {
        for (int k = 0; k <= qt; ++k) kts[nkt++] = k;
    }

    // ---- Q fragments (hi/lo), scale already folded in prep ----
    uint32_t qhi[8][4], qlo[8][4];
    {
        const float* qb = &g_qkv[(size_t)(t0 + mrow) * NQKV + head * HD];
#pragma unroll
        for (int ks = 0; ks < 8; ++ks) {
#pragma unroll
            for (int rg = 0; rg < 4; ++rg) {
                int row = r + (rg & 1) * 8;
                int col = ks * 16 + cc + (rg >> 1) * 8;
                float2 v = *(const float2*)&qb[(size_t)row * NQKV + col];
                uint32_t h = cvt_bf16x2(v.y, v.x);
                float f0 = __uint_as_float(h << 16);
                float f1 = __uint_as_float(h & 0xffff0000u);
                qhi[ks][rg] = h;
                qlo[ks][rg] = cvt_bf16x2(v.y - f1, v.x - f0);
            }
        }
    }

    // cp.async loader
    const __nv_bfloat16* srcKV[4] = { g_Khi, g_Klo, g_Vhi, g_Vlo };
    auto issue = [&](int ti, int buf) {
        int s0 = kts[ti] * 64;
#pragma unroll
        for (int q = 0; q < 16; ++q) {
            int idx = q * 256 + tid;
            int arr = idx >> 10;
            int rem = idx & 1023;
            int row = rem >> 4;
            int ch  = rem & 15;
            const __nv_bfloat16* src = srcKV[arr] + (size_t)(s0 + row) * (NKV * HD) + kvh * HD + ch * 8;
            uint32_t dst = smu + buf * ASTAGE + arr * ARR_B + row * APITCH + ch * 16;
            cp_async16(dst, src);
        }
    };

    // per-lane ldsm offsets
    const uint32_t koff = (lane & 7) * APITCH + (lane >> 3) * 16;
    const uint32_t voff = ((lane & 7) + ((lane >> 3) & 1) * 8) * APITCH + ((lane >> 3) >> 1) * 16;

    float oacc[16][4];
#pragma unroll
    for (int j = 0; j < 16; ++j)
#pragma unroll
        for (int q = 0; q < 4; ++q) oacc[j][q] = 0.f;
    float m0 = -3.0e38f, m1 = -3.0e38f, l0 = 0.f, l1 = 0.f;

    const int tr0 = t0 + mrow + r;
    const int tr1 = tr0 + 8;

    issue(0, 0); CP_COMMIT();

    for (int it = 0; it < nkt; ++it) {
        if (it + 1 < nkt) issue(it + 1, (it + 1) & 1);
        CP_COMMIT();
        CP_WAIT1();
        __syncthreads();

        const uint32_t kb = smu + (it & 1) * ASTAGE;
        const uint32_t vb = kb + 2 * ARR_B;
        const int s0 = kts[it] * 64;

        // ---- S = Q K^T (split, 3-term) ----
        float sacc[8][4];
#pragma unroll
        for (int j = 0; j < 8; ++j)
#pragma unroll
            for (int q = 0; q < 4; ++q) sacc[j][q] = 0.f;

#pragma unroll
        for (int j = 0; j < 8; ++j) {
            uint32_t jb = kb + j * (8 * APITCH) + koff;
#pragma unroll
            for (int k2 = 0; k2 < 4; ++k2) {
                uint32_t kh[4], kl[4];
                uint32_t a = jb + k2 * 64;
                ldsm_x4(kh, a);
                ldsm_x4(kl, a + ARR_B);
                mma_bf16(sacc[j], qhi[2 * k2], kh);
                mma_bf16(sacc[j], qhi[2 * k2], kl);
                mma_bf16(sacc[j], qlo[2 * k2], kh);
                mma_bf16(sacc[j], qhi[2 * k2 + 1], kh + 2);
                mma_bf16(sacc[j], qhi[2 * k2 + 1], kl + 2);
                mma_bf16(sacc[j], qlo[2 * k2 + 1], kh + 2);
            }
        }

        // ---- mask ----
#pragma unroll
        for (int j = 0; j < 8; ++j) {
            int sb0 = s0 + j * 8 + cc;
#pragma unroll
            for (int cx = 0; cx < 2; ++cx) {
                int s = sb0 + cx;
                bool v0 = (tr0 < MMETA) ? (s <= tr0)
                                        : ((s < MMETA) || ((s <= tr0) && (tr0 - s < WWIN)));
                bool v1 = (tr1 < MMETA) ? (s <= tr1)
                                        : ((s < MMETA) || ((s <= tr1) && (tr1 - s < WWIN)));
                if (!v0) sacc[j][cx]     = NEGV;
                if (!v1) sacc[j][cx + 2] = NEGV;
            }
        }

        // ---- online softmax ----
        float mx0 = NEGV, mx1 = NEGV;
#pragma unroll
        for (int j = 0; j < 8; ++j) {
            mx0 = fmaxf(mx0, fmaxf(sacc[j][0], sacc[j][1]));
            mx1 = fmaxf(mx1, fmaxf(sacc[j][2], sacc[j][3]));
        }
        mx0 = fmaxf(mx0, __shfl_xor_sync(0xffffffffu, mx0, 1));
        mx0 = fmaxf(mx0, __shfl_xor_sync(0xffffffffu, mx0, 2));
        mx1 = fmaxf(mx1, __shfl_xor_sync(0xffffffffu, mx1, 1));
        mx1 = fmaxf(mx1, __shfl_xor_sync(0xffffffffu, mx1, 2));

        float mn0 = fmaxf(m0, mx0);
        float mn1 = fmaxf(m1, mx1);
        float al0 = __expf(m0 - mn0);
        float al1 = __expf(m1 - mn1);
        m0 = mn0; m1 = mn1;

        float sum0 = 0.f, sum1 = 0.f;
#pragma unroll
        for (int j = 0; j < 8; ++j) {
            sacc[j][0] = __expf(sacc[j][0] - m0);
            sacc[j][1] = __expf(sacc[j][1] - m0);
            sacc[j][2] = __expf(sacc[j][2] - m1);
            sacc[j][3] = __expf(sacc[j][3] - m1);
            sum0 += sacc[j][0] + sacc[j][1];
            sum1 += sacc[j][2] + sacc[j][3];
        }
        sum0 += __shfl_xor_sync(0xffffffffu, sum0, 1);
        sum0 += __shfl_xor_sync(0xffffffffu, sum0, 2);
        sum1 += __shfl_xor_sync(0xffffffffu, sum1, 1);
        sum1 += __shfl_xor_sync(0xffffffffu, sum1, 2);
        l0 = l0 * al0 + sum0;
        l1 = l1 * al1 + sum1;

#pragma unroll
        for (int j = 0; j < 16; ++j) {
            oacc[j][0] *= al0; oacc[j][1] *= al0;
            oacc[j][2] *= al1; oacc[j][3] *= al1;
        }

        // ---- O += P V (split, 3-term), P packed in-register ----
#pragma unroll
        for (int kt = 0; kt < 4; ++kt) {
            uint32_t phi[4], plo[4];
#pragma unroll
            for (int hq = 0; hq < 2; ++hq) {      // hq=0 -> ntile 2kt, hq=1 -> 2kt+1
                const float* sj = sacc[2 * kt + hq];
                uint32_t h0 = cvt_bf16x2(sj[1], sj[0]);
                uint32_t h1 = cvt_bf16x2(sj[3], sj[2]);
                float a0 = __uint_as_float(h0 << 16);
                float a1 = __uint_as_float(h0 & 0xffff0000u);
                float b0 = __uint_as_float(h1 << 16);
                float b1 = __uint_as_float(h1 & 0xffff0000u);
                phi[2 * hq]     = h0;
                phi[2 * hq + 1] = h1;
                plo[2 * hq]     = cvt_bf16x2(sj[1] - a1, sj[0] - a0);
                plo[2 * hq + 1] = cvt_bf16x2(sj[3] - b1, sj[2] - b0);
            }
            uint32_t ktb = vb + kt * (16 * APITCH) + voff;
#pragma unroll
            for (int j2 = 0; j2 < 8; ++j2) {
                uint32_t vh[4], vl[4];
                uint32_t a = ktb + j2 * 32;
                ldsm_x4t(vh, a);
                ldsm_x4t(vl, a + ARR_B);
                mma_bf16(oacc[2 * j2], phi, vh);
                mma_bf16(oacc[2 * j2], phi, vl);
                mma_bf16(oacc[2 * j2], plo, vh);
                mma_bf16(oacc[2 * j2 + 1], phi, vh + 2);
                mma_bf16(oacc[2 * j2 + 1], phi, vl + 2);
                mma_bf16(oacc[2 * j2 + 1], plo, vh + 2);
            }
        }
        __syncthreads();
    }

    // ---- epilogue ----
    float inv0 = 1.0f / l0;
    float inv1 = 1.0f / l1;
    float* ob0 = &out[(size_t)tr0 * (NH * HD) + head * HD + cc];
    float* ob1 = &out[(size_t)tr1 * (NH * HD) + head * HD + cc];
#pragma unroll
    for (int j = 0; j < 16; ++j) {
        float2 v0 = { oacc[j][0] * inv0, oacc[j][1] * inv0 };
        float2 v1 = { oacc[j][2] * inv1, oacc[j][3] * inv1 };
        *(float2*)&ob0[j * 8] = v0;
        *(float2*)&ob1[j * 8] = v1;
    }
}

// ---------------------------------------------------------------------------
extern "C" void kernel_launch(void* const* d_in, const int* in_sizes, int n_in,
                              void* d_out, int out_size) {
    const float* hs   = (const float*)d_in[0];
    const float* w    = (const float*)d_in[1];
    const float* bias = (const float*)d_in[2];
    const int*   pos  = (const int*)d_in[3];
    float* out = (float*)d_out;

    int na = T_TOK * HS / 4;
    split_a_kernel<<<(na + 255) / 256, 256>>>(hs);
    split_w_kernel<<<dim3(NQKV / 32, HS / 32), dim3(32, 8)>>>(w);

    cudaFuncSetAttribute(qkv_mma_kernel, cudaFuncAttributeMaxDynamicSharedMemorySize, GEMM_SMEM);
    qkv_mma_kernel<<<dim3(NQKV / 128, T_TOK / 128), 256, GEMM_SMEM>>>(bias);

    int nprep = T_TOK * 24 * 64;
    prep_kernel<<<(nprep + 255) / 256, 256>>>(pos);

    cudaFuncSetAttribute(attn_mma_kernel, cudaFuncAttributeMaxDynamicSharedMemorySize, ATTN_SMEM);
    attn_mma_kernel<<<dim3(34, 8), 256, ATTN_SMEM>>>(out);
}